// round 1
// baseline (speedup 1.0000x reference)
#include <cuda_runtime.h>
#include <math.h>

#define BATCH 4
#define SEQ   2048
#define CH    512
#define NH    8
#define HD    64
#define NG    8
#define CPG   (CH/NG)   // 64

// ------------------------- scratch (static __device__, no allocs) ----------
__device__ float g_P1 [BATCH*SEQ*CH];                       // 16 MB
__device__ float g_P2 [BATCH*SEQ*CH];                       // 16 MB
__device__ float g_PEA[(size_t)BATCH*SEQ*SEQ];              // 64 MB
__device__ float g_QKV[(size_t)BATCH*SEQ*3*CH];             // 48 MB
__device__ float g_S  [(size_t)BATCH*NH*SEQ*SEQ];           // 512 MB
__device__ float g_O  [BATCH*SEQ*CH];                       // 16 MB

// ---------------------------------------------------------------------------
// Generic SGEMM:  C[M,N] = A[M,K] * B[N,K]^T   (both row-major, B transposed)
// 128x128 tile, BK=8, 256 threads, 8x8 per thread.
// EPI: 0 = none, 1 = +bias[col], 2 = sigmoid, 3 = *= scale*PE[row,col]
// Batch offsets: z1 = z/zdiv, z2 = z%zdiv;
//   A += z1*sA1 + z2*sA2;  B += z1*sB1 + z2*sB2;  C += z*sC;  PE += z1*sP
// ---------------------------------------------------------------------------
template<int EPI>
__global__ void __launch_bounds__(256)
gemm_abt(const float* __restrict__ Abase, const float* __restrict__ Bbase,
         float* __restrict__ Cbase, const float* __restrict__ bias,
         const float* __restrict__ pebase,
         int K, int lda, int ldb, int ldc,
         int zdiv, long sA1, long sA2, long sB1, long sB2, long sC, long sP,
         float scale)
{
    const int z  = blockIdx.z;
    const int z1 = z / zdiv;
    const int z2 = z - z1 * zdiv;
    const float* A  = Abase + z1 * sA1 + z2 * sA2;
    const float* Bm = Bbase + z1 * sB1 + z2 * sB2;
    float*       C  = Cbase + (long)z * sC;
    const float* P  = pebase + z1 * sP;

    __shared__ float As[8][132];
    __shared__ float Bs[8][132];

    const int tid = threadIdx.x;
    const int tx  = tid & 15;
    const int ty  = tid >> 4;

    const int rS = tid >> 1;
    const int c0 = (tid & 1) << 2;
    const float* aPtr = A  + (long)((blockIdx.y << 7) + rS) * lda + c0;
    const float* bPtr = Bm + (long)((blockIdx.x << 7) + rS) * ldb + c0;

    float acc[8][8];
#pragma unroll
    for (int i = 0; i < 8; i++)
#pragma unroll
        for (int j = 0; j < 8; j++) acc[i][j] = 0.f;

    for (int k0 = 0; k0 < K; k0 += 8) {
        float4 av = *(const float4*)(aPtr + k0);
        float4 bv = *(const float4*)(bPtr + k0);
        __syncthreads();
        As[c0+0][rS] = av.x; As[c0+1][rS] = av.y; As[c0+2][rS] = av.z; As[c0+3][rS] = av.w;
        Bs[c0+0][rS] = bv.x; Bs[c0+1][rS] = bv.y; Bs[c0+2][rS] = bv.z; Bs[c0+3][rS] = bv.w;
        __syncthreads();
#pragma unroll
        for (int kk = 0; kk < 8; kk++) {
            float4 a0 = *(const float4*)&As[kk][ty << 2];
            float4 a1 = *(const float4*)&As[kk][64 + (ty << 2)];
            float4 b0 = *(const float4*)&Bs[kk][tx << 2];
            float4 b1 = *(const float4*)&Bs[kk][64 + (tx << 2)];
            float a[8] = {a0.x, a0.y, a0.z, a0.w, a1.x, a1.y, a1.z, a1.w};
            float b[8] = {b0.x, b0.y, b0.z, b0.w, b1.x, b1.y, b1.z, b1.w};
#pragma unroll
            for (int i = 0; i < 8; i++)
#pragma unroll
                for (int j = 0; j < 8; j++)
                    acc[i][j] = fmaf(a[i], b[j], acc[i][j]);
        }
    }

    const int gr0 = blockIdx.y << 7;
    const int gc0 = blockIdx.x << 7;
#pragma unroll
    for (int i = 0; i < 8; i++) {
        const int ri   = (i < 4) ? ((ty << 2) + i) : (64 + (ty << 2) + i - 4);
        const int grow = gr0 + ri;
#pragma unroll
        for (int jq = 0; jq < 2; jq++) {
            const int cj = gc0 + ((jq == 0) ? (tx << 2) : (64 + (tx << 2)));
            float4 v;
            v.x = acc[i][jq*4+0]; v.y = acc[i][jq*4+1];
            v.z = acc[i][jq*4+2]; v.w = acc[i][jq*4+3];
            if (EPI == 1) {
                v.x += bias[cj];   v.y += bias[cj+1];
                v.z += bias[cj+2]; v.w += bias[cj+3];
            } else if (EPI == 2) {
                v.x = 1.f/(1.f+__expf(-v.x)); v.y = 1.f/(1.f+__expf(-v.y));
                v.z = 1.f/(1.f+__expf(-v.z)); v.w = 1.f/(1.f+__expf(-v.w));
            } else if (EPI == 3) {
                float4 p = *(const float4*)(P + (long)grow * SEQ + cj);
                v.x *= scale * p.x; v.y *= scale * p.y;
                v.z *= scale * p.z; v.w *= scale * p.w;
            }
            *(float4*)(C + (long)grow * ldc + cj) = v;
        }
    }
}

// ---------------------------------------------------------------------------
// attn @ V :  per z=(b*NH+h), O[b, n, h*HD+d] = sum_m S[z][n,m] * V[b,m,h*HD+d]
// tile 128(M) x 64(N=HD), BK=16, 256 threads, 8x4 per thread.
// ---------------------------------------------------------------------------
__global__ void __launch_bounds__(256)
gemm_av(const float* __restrict__ Sbase, const float* __restrict__ QKVbase,
        float* __restrict__ Obase)
{
    const int z = blockIdx.z;
    const int b = z >> 3;
    const int h = z & 7;
    const float* A = Sbase + (long)z * SEQ * SEQ;                    // [2048,2048]
    const float* V = QKVbase + (long)b * SEQ * 3 * CH + 2 * CH + h * HD; // ld=3*CH
    float*       C = Obase + (long)b * SEQ * CH + h * HD;            // ld=CH

    __shared__ float As[16][132];
    __shared__ float Bs[16][64];

    const int tid = threadIdx.x;
    const int tx  = tid & 15;
    const int ty  = tid >> 4;
    const int gr0 = blockIdx.x << 7;

    float acc[8][4];
#pragma unroll
    for (int i = 0; i < 8; i++)
#pragma unroll
        for (int j = 0; j < 4; j++) acc[i][j] = 0.f;

    const int f0 = tid, f1 = tid + 256;
    const int ar0 = f0 >> 2, ac0 = (f0 & 3) << 2;
    const int ar1 = f1 >> 2, ac1 = (f1 & 3) << 2;
    const int br  = tid >> 4, bc = (tid & 15) << 2;

    const float* aP0 = A + (long)(gr0 + ar0) * SEQ + ac0;
    const float* aP1 = A + (long)(gr0 + ar1) * SEQ + ac1;
    const float* vP  = V + (long)br * (3 * CH) + bc;

    for (int k0 = 0; k0 < SEQ; k0 += 16) {
        float4 a0 = *(const float4*)(aP0 + k0);
        float4 a1 = *(const float4*)(aP1 + k0);
        float4 bv = *(const float4*)(vP + (long)k0 * (3 * CH));
        __syncthreads();
        As[ac0+0][ar0] = a0.x; As[ac0+1][ar0] = a0.y;
        As[ac0+2][ar0] = a0.z; As[ac0+3][ar0] = a0.w;
        As[ac1+0][ar1] = a1.x; As[ac1+1][ar1] = a1.y;
        As[ac1+2][ar1] = a1.z; As[ac1+3][ar1] = a1.w;
        *(float4*)&Bs[br][bc] = bv;
        __syncthreads();
#pragma unroll
        for (int kk = 0; kk < 16; kk++) {
            float4 x0 = *(const float4*)&As[kk][ty << 2];
            float4 x1 = *(const float4*)&As[kk][64 + (ty << 2)];
            float4 y  = *(const float4*)&Bs[kk][tx << 2];
            float a[8]  = {x0.x, x0.y, x0.z, x0.w, x1.x, x1.y, x1.z, x1.w};
            float bb[4] = {y.x, y.y, y.z, y.w};
#pragma unroll
            for (int i = 0; i < 8; i++)
#pragma unroll
                for (int j = 0; j < 4; j++)
                    acc[i][j] = fmaf(a[i], bb[j], acc[i][j]);
        }
    }

#pragma unroll
    for (int i = 0; i < 8; i++) {
        const int ri = (i < 4) ? ((ty << 2) + i) : (64 + (ty << 2) + i - 4);
        float4 v;
        v.x = acc[i][0]; v.y = acc[i][1]; v.z = acc[i][2]; v.w = acc[i][3];
        *(float4*)(C + (long)(gr0 + ri) * CH + (tx << 2)) = v;
    }
}

// ---------------------------------------------------------------------------
// Row softmax over 2048 elems, one block (256 thr) per row, in-place.
// ---------------------------------------------------------------------------
__global__ void __launch_bounds__(256)
softmax_rows(float* __restrict__ S)
{
    float4* p4 = (float4*)(S + (long)blockIdx.x * SEQ);
    const int tid = threadIdx.x;
    float4 v0 = p4[tid];
    float4 v1 = p4[tid + 256];

    __shared__ float sh[256];
    float m = fmaxf(fmaxf(fmaxf(v0.x, v0.y), fmaxf(v0.z, v0.w)),
                    fmaxf(fmaxf(v1.x, v1.y), fmaxf(v1.z, v1.w)));
    sh[tid] = m; __syncthreads();
    for (int s = 128; s > 0; s >>= 1) {
        if (tid < s) sh[tid] = fmaxf(sh[tid], sh[tid + s]);
        __syncthreads();
    }
    const float mx = sh[0];
    __syncthreads();

    v0.x = __expf(v0.x - mx); v0.y = __expf(v0.y - mx);
    v0.z = __expf(v0.z - mx); v0.w = __expf(v0.w - mx);
    v1.x = __expf(v1.x - mx); v1.y = __expf(v1.y - mx);
    v1.z = __expf(v1.z - mx); v1.w = __expf(v1.w - mx);

    float sum = v0.x + v0.y + v0.z + v0.w + v1.x + v1.y + v1.z + v1.w;
    sh[tid] = sum; __syncthreads();
    for (int s = 128; s > 0; s >>= 1) {
        if (tid < s) sh[tid] += sh[tid + s];
        __syncthreads();
    }
    const float inv = 1.f / sh[0];

    v0.x *= inv; v0.y *= inv; v0.z *= inv; v0.w *= inv;
    v1.x *= inv; v1.y *= inv; v1.z *= inv; v1.w *= inv;
    p4[tid] = v0; p4[tid + 256] = v1;
}

// ---------------------------------------------------------------------------
// GroupNorm (torch semantics): stats over (C/G channels x N positions) per
// (batch, group). One block per (b,g), in-place on [B, N, C] layout.
// ---------------------------------------------------------------------------
__global__ void __launch_bounds__(512)
groupnorm_inplace(float* __restrict__ Y, const float* __restrict__ gamma,
                  const float* __restrict__ beta)
{
    const int b = blockIdx.x >> 3;
    const int g = blockIdx.x & 7;
    float* base = Y + (long)b * SEQ * CH + g * CPG;
    const int tid = threadIdx.x;
    const int TOT = SEQ * CPG;   // 131072

    float s = 0.f, ss = 0.f;
    for (int idx = tid; idx < TOT; idx += 512) {
        const int n = idx >> 6, c = idx & 63;
        const float v = base[(long)n * CH + c];
        s += v; ss += v * v;
    }
    __shared__ float sh1[512], sh2[512];
    sh1[tid] = s; sh2[tid] = ss; __syncthreads();
    for (int st = 256; st > 0; st >>= 1) {
        if (tid < st) { sh1[tid] += sh1[tid + st]; sh2[tid] += sh2[tid + st]; }
        __syncthreads();
    }
    const float mean = sh1[0] / TOT;
    const float var  = sh2[0] / TOT - mean * mean;
    const float inv  = rsqrtf(var + 1e-5f);

    for (int idx = tid; idx < TOT; idx += 512) {
        const int n = idx >> 6, c = idx & 63;
        const int ch = g * CPG + c;
        const float v = base[(long)n * CH + c];
        base[(long)n * CH + c] = (v - mean) * inv * gamma[ch] + beta[ch];
    }
}

// ---------------------------------------------------------------------------
extern "C" void kernel_launch(void* const* d_in, const int* in_sizes, int n_in,
                              void* d_out, int out_size)
{
    const float* x       = (const float*)d_in[0];
    const float* pe      = (const float*)d_in[1];
    const float* qkv_w   = (const float*)d_in[2];
    const float* proj_w  = (const float*)d_in[3];
    const float* proj_b  = (const float*)d_in[4];
    const float* conv1_w = (const float*)d_in[5];
    const float* conv1_b = (const float*)d_in[6];
    const float* gn1_g   = (const float*)d_in[7];
    const float* gn1_b   = (const float*)d_in[8];
    const float* conv2_w = (const float*)d_in[9];
    const float* conv2_b = (const float*)d_in[10];
    const float* gn2_g   = (const float*)d_in[11];
    const float* gn2_b   = (const float*)d_in[12];
    float* out = (float*)d_out;

    float *P1, *P2, *PEA, *QKV, *S, *O;
    cudaGetSymbolAddress((void**)&P1,  g_P1);
    cudaGetSymbolAddress((void**)&P2,  g_P2);
    cudaGetSymbolAddress((void**)&PEA, g_PEA);
    cudaGetSymbolAddress((void**)&QKV, g_QKV);
    cudaGetSymbolAddress((void**)&S,   g_S);
    cudaGetSymbolAddress((void**)&O,   g_O);

    const dim3 blk(256);
    const float scale = 0.125f;   // HD^-0.5

    // conv1/conv2 (1x1 conv == GEMM over channels), [8192,512] x [512,512]^T
    gemm_abt<1><<<dim3(4, 64, 1), blk>>>(pe, conv1_w, P1, conv1_b, nullptr,
        512, 512, 512, 512, 1, 0, 0, 0, 0, 0, 0, 0.f);
    gemm_abt<1><<<dim3(4, 64, 1), blk>>>(pe, conv2_w, P2, conv2_b, nullptr,
        512, 512, 512, 512, 1, 0, 0, 0, 0, 0, 0, 0.f);

    groupnorm_inplace<<<32, 512>>>(P1, gn1_g, gn1_b);
    groupnorm_inplace<<<32, 512>>>(P2, gn2_g, gn2_b);

    // pe_attn[b] = sigmoid(P1[b] @ P2[b]^T), per-batch [2048,512]x[2048,512]^T
    gemm_abt<2><<<dim3(16, 16, BATCH), blk>>>(P1, P2, PEA, nullptr, nullptr,
        512, 512, 512, 2048, 1,
        (long)SEQ * CH, 0, (long)SEQ * CH, 0, (long)SEQ * SEQ, 0, 0.f);

    // qkv = x @ qkv_w^T, [8192,512] x [1536,512]^T
    gemm_abt<0><<<dim3(12, 64, 1), blk>>>(x, qkv_w, QKV, nullptr, nullptr,
        512, 512, 512, 3 * CH, 1, 0, 0, 0, 0, 0, 0, 0.f);

    // S[z] = (Q[b,h] @ K[b,h]^T) * scale * PEA[b],  z = b*NH+h, K-dim = 64
    gemm_abt<3><<<dim3(16, 16, BATCH * NH), blk>>>(QKV, QKV + CH, S, nullptr, PEA,
        HD, 3 * CH, 3 * CH, 2048, NH,
        (long)SEQ * 3 * CH, HD, (long)SEQ * 3 * CH, HD,
        (long)SEQ * SEQ, (long)SEQ * SEQ, scale);

    softmax_rows<<<BATCH * NH * SEQ, 256>>>(S);

    // O[b, n, h*HD+d] = softmax(S)[z] @ V[b,h]
    gemm_av<<<dim3(16, 1, BATCH * NH), blk>>>(S, QKV, O);

    // out = O @ proj_w^T + proj_b
    gemm_abt<1><<<dim3(4, 64, 1), blk>>>(O, proj_w, out, proj_b, nullptr,
        512, 512, 512, 512, 1, 0, 0, 0, 0, 0, 0, 0.f);
}

// round 2
// speedup vs baseline: 1.6446x; 1.6446x over previous
#include <cuda_runtime.h>
#include <math.h>

#define BATCH 4
#define SEQ   2048
#define CH    512
#define NH    8
#define HD    64
#define NG    8
#define CPG   (CH/NG)   // 64

// ------------------------- scratch (static __device__, no allocs) ----------
__device__ float g_P1 [BATCH*SEQ*CH];                       // 16 MB
__device__ float g_P2 [BATCH*SEQ*CH];                       // 16 MB
__device__ float g_PEA[(size_t)BATCH*SEQ*SEQ];              // 64 MB
__device__ float g_QKV[(size_t)BATCH*SEQ*3*CH];             // 48 MB
__device__ float g_S  [(size_t)BATCH*NH*SEQ*SEQ];           // 512 MB
__device__ float g_O  [BATCH*SEQ*CH];                       // 16 MB
__device__ float g_GNP[BATCH*NG*8*2];                       // GN partials

// ---------------------------------------------------------------------------
__device__ __forceinline__ unsigned f2tf(float x) {
    unsigned u;
    asm("cvt.rna.tf32.f32 %0, %1;" : "=r"(u) : "f"(x));
    return u;
}

__device__ __forceinline__ void mma_tf32(float* d, const unsigned* a, const unsigned* b) {
    asm volatile(
        "mma.sync.aligned.m16n8k8.row.col.f32.tf32.tf32.f32 "
        "{%0,%1,%2,%3}, {%4,%5,%6,%7}, {%8,%9}, {%0,%1,%2,%3};"
        : "+f"(d[0]), "+f"(d[1]), "+f"(d[2]), "+f"(d[3])
        : "r"(a[0]), "r"(a[1]), "r"(a[2]), "r"(a[3]), "r"(b[0]), "r"(b[1]));
}

// ---------------------------------------------------------------------------
// TF32 tensor-core GEMM:  C[M,N] = A[M,K] * B[N,K]^T  (row-major, B transposed)
// 128x128 tile, BK=16, 256 threads (8 warps 4x2), warp tile 32x64.
// EPI: 0 none, 1 +bias[col], 2 sigmoid, 3 *= scale*PE[row,col]
// ---------------------------------------------------------------------------
template<int EPI>
__global__ void __launch_bounds__(256)
gemm_tf32(const float* __restrict__ Abase, const float* __restrict__ Bbase,
          float* __restrict__ Cbase, const float* __restrict__ bias,
          const float* __restrict__ pebase,
          int K, int lda, int ldb, int ldc,
          int zdiv, long sA1, long sA2, long sB1, long sB2, long sC, long sP,
          float scale)
{
    const int z  = blockIdx.z;
    const int z1 = z / zdiv;
    const int z2 = z - z1 * zdiv;
    const float* A  = Abase + z1 * sA1 + z2 * sA2;
    const float* Bm = Bbase + z1 * sB1 + z2 * sB2;
    float*       C  = Cbase + (long)z * sC;
    const float* P  = pebase + z1 * sP;

    __shared__ unsigned AsU[128 * 17];
    __shared__ unsigned BsU[128 * 17];

    const int tid  = threadIdx.x;
    const int wid  = tid >> 5;
    const int lane = tid & 31;
    const int g    = lane >> 2;        // groupID
    const int tg   = lane & 3;         // thread-in-group
    const int wm   = (wid & 3) * 32;   // warp m offset
    const int wn   = (wid >> 2) * 64;  // warp n offset

    const int lm = tid >> 1;           // loader row 0..127
    const int lk = (tid & 1) * 8;      // loader k base 0 or 8

    const int gr0 = blockIdx.y << 7;
    const int gc0 = blockIdx.x << 7;

    const float* aPtr = A  + (long)(gr0 + lm) * lda + lk;
    const float* bPtr = Bm + (long)(gc0 + lm) * ldb + lk;

    float acc[2][8][4];
#pragma unroll
    for (int i = 0; i < 2; i++)
#pragma unroll
        for (int j = 0; j < 8; j++)
#pragma unroll
            for (int q = 0; q < 4; q++) acc[i][j][q] = 0.f;

    for (int k0 = 0; k0 < K; k0 += 16) {
        float4 a0 = *(const float4*)(aPtr + k0);
        float4 a1 = *(const float4*)(aPtr + k0 + 4);
        float4 b0 = *(const float4*)(bPtr + k0);
        float4 b1 = *(const float4*)(bPtr + k0 + 4);
        __syncthreads();
        unsigned* ap = &AsU[lm * 17 + lk];
        unsigned* bp = &BsU[lm * 17 + lk];
        ap[0] = f2tf(a0.x); ap[1] = f2tf(a0.y); ap[2] = f2tf(a0.z); ap[3] = f2tf(a0.w);
        ap[4] = f2tf(a1.x); ap[5] = f2tf(a1.y); ap[6] = f2tf(a1.z); ap[7] = f2tf(a1.w);
        bp[0] = f2tf(b0.x); bp[1] = f2tf(b0.y); bp[2] = f2tf(b0.z); bp[3] = f2tf(b0.w);
        bp[4] = f2tf(b1.x); bp[5] = f2tf(b1.y); bp[6] = f2tf(b1.z); bp[7] = f2tf(b1.w);
        __syncthreads();

#pragma unroll
        for (int kk = 0; kk < 16; kk += 8) {
            unsigned afr[2][4], bfr[8][2];
#pragma unroll
            for (int mf = 0; mf < 2; mf++) {
                const int r0 = wm + mf * 16 + g;
                afr[mf][0] = AsU[r0 * 17 + kk + tg];
                afr[mf][1] = AsU[(r0 + 8) * 17 + kk + tg];
                afr[mf][2] = AsU[r0 * 17 + kk + tg + 4];
                afr[mf][3] = AsU[(r0 + 8) * 17 + kk + tg + 4];
            }
#pragma unroll
            for (int nf = 0; nf < 8; nf++) {
                const int c0 = wn + nf * 8 + g;
                bfr[nf][0] = BsU[c0 * 17 + kk + tg];
                bfr[nf][1] = BsU[c0 * 17 + kk + tg + 4];
            }
#pragma unroll
            for (int mf = 0; mf < 2; mf++)
#pragma unroll
                for (int nf = 0; nf < 8; nf++)
                    mma_tf32(acc[mf][nf], afr[mf], bfr[nf]);
        }
    }

#pragma unroll
    for (int mf = 0; mf < 2; mf++) {
#pragma unroll
        for (int nf = 0; nf < 8; nf++) {
            const int rlo = gr0 + wm + mf * 16 + g;
            const int rhi = rlo + 8;
            const int col = gc0 + wn + nf * 8 + 2 * tg;
            float2 vlo = make_float2(acc[mf][nf][0], acc[mf][nf][1]);
            float2 vhi = make_float2(acc[mf][nf][2], acc[mf][nf][3]);
            if (EPI == 1) {
                const float b0v = bias[col], b1v = bias[col + 1];
                vlo.x += b0v; vlo.y += b1v; vhi.x += b0v; vhi.y += b1v;
            } else if (EPI == 2) {
                vlo.x = 1.f / (1.f + __expf(-vlo.x));
                vlo.y = 1.f / (1.f + __expf(-vlo.y));
                vhi.x = 1.f / (1.f + __expf(-vhi.x));
                vhi.y = 1.f / (1.f + __expf(-vhi.y));
            } else if (EPI == 3) {
                float2 plo = *(const float2*)(P + (long)rlo * SEQ + col);
                float2 phi = *(const float2*)(P + (long)rhi * SEQ + col);
                vlo.x *= scale * plo.x; vlo.y *= scale * plo.y;
                vhi.x *= scale * phi.x; vhi.y *= scale * phi.y;
            }
            *(float2*)(C + (long)rlo * ldc + col) = vlo;
            *(float2*)(C + (long)rhi * ldc + col) = vhi;
        }
    }
}

// ---------------------------------------------------------------------------
// attn @ V (TF32): per z=(b*NH+h), O[b,n,h*HD+d] = sum_m S[z][n,m]*V[b,m,h*HD+d]
// tile 128(M) x 64(N=HD), BK=16, 256 threads (8 warps, 16 rows each).
// ---------------------------------------------------------------------------
__global__ void __launch_bounds__(256)
gemm_av(const float* __restrict__ Sbase, const float* __restrict__ QKVbase,
        float* __restrict__ Obase)
{
    const int z = blockIdx.z;
    const int b = z >> 3;
    const int h = z & 7;
    const float* A = Sbase + (long)z * SEQ * SEQ;
    const float* V = QKVbase + (long)b * SEQ * 3 * CH + 2 * CH + h * HD;
    float*       C = Obase + (long)b * SEQ * CH + h * HD;

    __shared__ unsigned SsU[128 * 17];
    __shared__ unsigned VsU[16 * 72];

    const int tid  = threadIdx.x;
    const int wid  = tid >> 5;
    const int lane = tid & 31;
    const int g    = lane >> 2;
    const int tg   = lane & 3;

    const int lm = tid >> 1;
    const int lk = (tid & 1) * 8;
    const int vk = tid >> 4;            // 0..15
    const int vd = (tid & 15) * 4;      // 0..60

    const int gr0 = blockIdx.x << 7;

    const float* aPtr = A + (long)(gr0 + lm) * SEQ + lk;
    const float* vPtr = V + (long)vk * (3 * CH) + vd;

    float acc[8][4];
#pragma unroll
    for (int j = 0; j < 8; j++)
#pragma unroll
        for (int q = 0; q < 4; q++) acc[j][q] = 0.f;

    for (int k0 = 0; k0 < SEQ; k0 += 16) {
        float4 a0 = *(const float4*)(aPtr + k0);
        float4 a1 = *(const float4*)(aPtr + k0 + 4);
        float4 vv = *(const float4*)(vPtr + (long)k0 * (3 * CH));
        __syncthreads();
        unsigned* ap = &SsU[lm * 17 + lk];
        ap[0] = f2tf(a0.x); ap[1] = f2tf(a0.y); ap[2] = f2tf(a0.z); ap[3] = f2tf(a0.w);
        ap[4] = f2tf(a1.x); ap[5] = f2tf(a1.y); ap[6] = f2tf(a1.z); ap[7] = f2tf(a1.w);
        unsigned* vp = &VsU[vk * 72 + vd];
        vp[0] = f2tf(vv.x); vp[1] = f2tf(vv.y); vp[2] = f2tf(vv.z); vp[3] = f2tf(vv.w);
        __syncthreads();

#pragma unroll
        for (int kk = 0; kk < 16; kk += 8) {
            unsigned afr[4], bfr[8][2];
            const int r0 = wid * 16 + g;
            afr[0] = SsU[r0 * 17 + kk + tg];
            afr[1] = SsU[(r0 + 8) * 17 + kk + tg];
            afr[2] = SsU[r0 * 17 + kk + tg + 4];
            afr[3] = SsU[(r0 + 8) * 17 + kk + tg + 4];
#pragma unroll
            for (int nf = 0; nf < 8; nf++) {
                bfr[nf][0] = VsU[(kk + tg) * 72 + nf * 8 + g];
                bfr[nf][1] = VsU[(kk + tg + 4) * 72 + nf * 8 + g];
            }
#pragma unroll
            for (int nf = 0; nf < 8; nf++)
                mma_tf32(acc[nf], afr, bfr[nf]);
        }
    }

#pragma unroll
    for (int nf = 0; nf < 8; nf++) {
        const int rlo = gr0 + wid * 16 + g;
        const int rhi = rlo + 8;
        const int col = nf * 8 + 2 * tg;
        *(float2*)(C + (long)rlo * CH + col) = make_float2(acc[nf][0], acc[nf][1]);
        *(float2*)(C + (long)rhi * CH + col) = make_float2(acc[nf][2], acc[nf][3]);
    }
}

// ---------------------------------------------------------------------------
// Row softmax over 2048 elems, one block (256 thr) per row, in-place.
// ---------------------------------------------------------------------------
__global__ void __launch_bounds__(256)
softmax_rows(float* __restrict__ S)
{
    float4* p4 = (float4*)(S + (long)blockIdx.x * SEQ);
    const int tid = threadIdx.x;
    float4 v0 = p4[tid];
    float4 v1 = p4[tid + 256];

    __shared__ float sh[256];
    float m = fmaxf(fmaxf(fmaxf(v0.x, v0.y), fmaxf(v0.z, v0.w)),
                    fmaxf(fmaxf(v1.x, v1.y), fmaxf(v1.z, v1.w)));
    sh[tid] = m; __syncthreads();
    for (int s = 128; s > 0; s >>= 1) {
        if (tid < s) sh[tid] = fmaxf(sh[tid], sh[tid + s]);
        __syncthreads();
    }
    const float mx = sh[0];
    __syncthreads();

    v0.x = __expf(v0.x - mx); v0.y = __expf(v0.y - mx);
    v0.z = __expf(v0.z - mx); v0.w = __expf(v0.w - mx);
    v1.x = __expf(v1.x - mx); v1.y = __expf(v1.y - mx);
    v1.z = __expf(v1.z - mx); v1.w = __expf(v1.w - mx);

    float sum = v0.x + v0.y + v0.z + v0.w + v1.x + v1.y + v1.z + v1.w;
    sh[tid] = sum; __syncthreads();
    for (int s = 128; s > 0; s >>= 1) {
        if (tid < s) sh[tid] += sh[tid + s];
        __syncthreads();
    }
    const float inv = 1.f / sh[0];

    v0.x *= inv; v0.y *= inv; v0.z *= inv; v0.w *= inv;
    v1.x *= inv; v1.y *= inv; v1.z *= inv; v1.w *= inv;
    p4[tid] = v0; p4[tid + 256] = v1;
}

// ---------------------------------------------------------------------------
// GroupNorm split for full-chip occupancy (deterministic, no float atomics).
// Pass 1: 8 slabs per (b,g) -> partial (sum, sumsq).
// Pass 2: 16 blocks per (b,g) fold partials + normalize.
// ---------------------------------------------------------------------------
__global__ void __launch_bounds__(256)
gn_partial(const float* __restrict__ Y, float* __restrict__ part)
{
    const int slab = blockIdx.x;          // 0..7
    const int bg   = blockIdx.y;          // 0..31
    const int b = bg >> 3, g = bg & 7;
    const float* base = Y + (long)b * SEQ * CH + g * CPG;
    const int tid = threadIdx.x;
    const int n0 = slab * 256;            // 256 positions per slab

    float s = 0.f, ss = 0.f;
    // 256 pos x 64 ch = 16384 elems = 4096 float4; 256 threads -> 16 each
    for (int i = tid; i < 4096; i += 256) {
        const int n = n0 + (i >> 4);
        const int c = (i & 15) * 4;
        float4 v = *(const float4*)(base + (long)n * CH + c);
        s  += v.x + v.y + v.z + v.w;
        ss += v.x * v.x + v.y * v.y + v.z * v.z + v.w * v.w;
    }
    __shared__ float sh1[256], sh2[256];
    sh1[tid] = s; sh2[tid] = ss; __syncthreads();
    for (int st = 128; st > 0; st >>= 1) {
        if (tid < st) { sh1[tid] += sh1[tid + st]; sh2[tid] += sh2[tid + st]; }
        __syncthreads();
    }
    if (tid == 0) {
        part[(bg * 8 + slab) * 2 + 0] = sh1[0];
        part[(bg * 8 + slab) * 2 + 1] = sh2[0];
    }
}

__global__ void __launch_bounds__(256)
gn_apply(float* __restrict__ Y, const float* __restrict__ part,
         const float* __restrict__ gamma, const float* __restrict__ beta)
{
    const int sl = blockIdx.x;            // 0..15
    const int bg = blockIdx.y;            // 0..31
    const int b = bg >> 3, g = bg & 7;
    float* base = Y + (long)b * SEQ * CH + g * CPG;
    const int tid = threadIdx.x;

    float s = 0.f, ss = 0.f;
#pragma unroll
    for (int i = 0; i < 8; i++) {
        s  += part[(bg * 8 + i) * 2 + 0];
        ss += part[(bg * 8 + i) * 2 + 1];
    }
    const float TOT  = (float)(SEQ * CPG);
    const float mean = s / TOT;
    const float var  = ss / TOT - mean * mean;
    const float inv  = rsqrtf(var + 1e-5f);

    const int n0 = sl * 128;              // 128 positions per block
    // 128 pos x 64 ch = 2048 float4
    for (int i = tid; i < 2048; i += 256) {
        const int n = n0 + (i >> 4);
        const int c = (i & 15) * 4;
        float4 v = *(float4*)(base + (long)n * CH + c);
        const int ch = g * CPG + c;
        v.x = (v.x - mean) * inv * gamma[ch]     + beta[ch];
        v.y = (v.y - mean) * inv * gamma[ch + 1] + beta[ch + 1];
        v.z = (v.z - mean) * inv * gamma[ch + 2] + beta[ch + 2];
        v.w = (v.w - mean) * inv * gamma[ch + 3] + beta[ch + 3];
        *(float4*)(base + (long)n * CH + c) = v;
    }
}

// ---------------------------------------------------------------------------
extern "C" void kernel_launch(void* const* d_in, const int* in_sizes, int n_in,
                              void* d_out, int out_size)
{
    const float* x       = (const float*)d_in[0];
    const float* pe      = (const float*)d_in[1];
    const float* qkv_w   = (const float*)d_in[2];
    const float* proj_w  = (const float*)d_in[3];
    const float* proj_b  = (const float*)d_in[4];
    const float* conv1_w = (const float*)d_in[5];
    const float* conv1_b = (const float*)d_in[6];
    const float* gn1_g   = (const float*)d_in[7];
    const float* gn1_b   = (const float*)d_in[8];
    const float* conv2_w = (const float*)d_in[9];
    const float* conv2_b = (const float*)d_in[10];
    const float* gn2_g   = (const float*)d_in[11];
    const float* gn2_b   = (const float*)d_in[12];
    float* out = (float*)d_out;

    float *P1, *P2, *PEA, *QKV, *S, *O, *GNP;
    cudaGetSymbolAddress((void**)&P1,  g_P1);
    cudaGetSymbolAddress((void**)&P2,  g_P2);
    cudaGetSymbolAddress((void**)&PEA, g_PEA);
    cudaGetSymbolAddress((void**)&QKV, g_QKV);
    cudaGetSymbolAddress((void**)&S,   g_S);
    cudaGetSymbolAddress((void**)&O,   g_O);
    cudaGetSymbolAddress((void**)&GNP, g_GNP);

    const dim3 blk(256);
    const float scale = 0.125f;   // HD^-0.5

    // conv1/conv2 (1x1 conv == GEMM over channels), [8192,512] x [512,512]^T
    gemm_tf32<1><<<dim3(4, 64, 1), blk>>>(pe, conv1_w, P1, conv1_b, nullptr,
        512, 512, 512, 512, 1, 0, 0, 0, 0, 0, 0, 0.f);
    gemm_tf32<1><<<dim3(4, 64, 1), blk>>>(pe, conv2_w, P2, conv2_b, nullptr,
        512, 512, 512, 512, 1, 0, 0, 0, 0, 0, 0, 0.f);

    gn_partial<<<dim3(8, 32), blk>>>(P1, GNP);
    gn_apply  <<<dim3(16, 32), blk>>>(P1, GNP, gn1_g, gn1_b);
    gn_partial<<<dim3(8, 32), blk>>>(P2, GNP);
    gn_apply  <<<dim3(16, 32), blk>>>(P2, GNP, gn2_g, gn2_b);

    // pe_attn[b] = sigmoid(P1[b] @ P2[b]^T)
    gemm_tf32<2><<<dim3(16, 16, BATCH), blk>>>(P1, P2, PEA, nullptr, nullptr,
        512, 512, 512, 2048, 1,
        (long)SEQ * CH, 0, (long)SEQ * CH, 0, (long)SEQ * SEQ, 0, 0.f);

    // qkv = x @ qkv_w^T
    gemm_tf32<0><<<dim3(12, 64, 1), blk>>>(x, qkv_w, QKV, nullptr, nullptr,
        512, 512, 512, 3 * CH, 1, 0, 0, 0, 0, 0, 0, 0.f);

    // S[z] = (Q[b,h] @ K[b,h]^T) * scale * PEA[b]
    gemm_tf32<3><<<dim3(16, 16, BATCH * NH), blk>>>(QKV, QKV + CH, S, nullptr, PEA,
        HD, 3 * CH, 3 * CH, 2048, NH,
        (long)SEQ * 3 * CH, HD, (long)SEQ * 3 * CH, HD,
        (long)SEQ * SEQ, (long)SEQ * SEQ, scale);

    softmax_rows<<<BATCH * NH * SEQ, 256>>>(S);

    // O = softmax(S) @ V
    gemm_av<<<dim3(16, 1, BATCH * NH), blk>>>(S, QKV, O);

    // out = O @ proj_w^T + proj_b
    gemm_tf32<1><<<dim3(4, 64, 1), blk>>>(O, proj_w, out, proj_b, nullptr,
        512, 512, 512, 512, 1, 0, 0, 0, 0, 0, 0, 0.f);
}

// round 6
// speedup vs baseline: 1.8480x; 1.1236x over previous
#include <cuda_runtime.h>
#include <math.h>

#define BATCH 4
#define SEQ   2048
#define CH    512
#define NH    8
#define HD    64
#define NG    8
#define CPG   (CH/NG)   // 64

// ------------------------- scratch (static __device__, no allocs) ----------
__device__ float g_P1 [BATCH*SEQ*CH];                       // 16 MB
__device__ float g_P2 [BATCH*SEQ*CH];                       // 16 MB
__device__ float g_PEA[(size_t)BATCH*SEQ*SEQ];              // 64 MB
__device__ float g_QKV[(size_t)BATCH*SEQ*3*CH];             // 48 MB
__device__ float g_O  [BATCH*SEQ*CH];                       // 16 MB
__device__ float g_GNP[BATCH*NG*8*2];                       // GN partials

// ---------------------------------------------------------------------------
__device__ __forceinline__ unsigned f2tf(float x) {
    unsigned u;
    asm("cvt.rna.tf32.f32 %0, %1;" : "=r"(u) : "f"(x));
    return u;
}

__device__ __forceinline__ void mma_tf32(float* d, const unsigned* a, const unsigned* b) {
    asm volatile(
        "mma.sync.aligned.m16n8k8.row.col.f32.tf32.tf32.f32 "
        "{%0,%1,%2,%3}, {%4,%5,%6,%7}, {%8,%9}, {%0,%1,%2,%3};"
        : "+f"(d[0]), "+f"(d[1]), "+f"(d[2]), "+f"(d[3])
        : "r"(a[0]), "r"(a[1]), "r"(a[2]), "r"(a[3]), "r"(b[0]), "r"(b[1]));
}

// ---------------------------------------------------------------------------
// TF32 tensor-core GEMM:  C[M,N] = A[M,K] * B[N,K]^T  (row-major, B transposed)
// 128x128 tile, BK=16, 256 threads (8 warps 4x2), warp tile 32x64.
// EPI: 0 none, 1 +bias[col], 2 sigmoid
// ---------------------------------------------------------------------------
template<int EPI>
__global__ void __launch_bounds__(256)
gemm_tf32(const float* __restrict__ Abase, const float* __restrict__ Bbase,
          float* __restrict__ Cbase, const float* __restrict__ bias,
          int K, int lda, int ldb, int ldc,
          long sA, long sB, long sC)
{
    const int z  = blockIdx.z;
    const float* A  = Abase + z * sA;
    const float* Bm = Bbase + z * sB;
    float*       C  = Cbase + (long)z * sC;

    __shared__ unsigned AsU[128 * 17];
    __shared__ unsigned BsU[128 * 17];

    const int tid  = threadIdx.x;
    const int wid  = tid >> 5;
    const int lane = tid & 31;
    const int g    = lane >> 2;
    const int tg   = lane & 3;
    const int wm   = (wid & 3) * 32;
    const int wn   = (wid >> 2) * 64;

    const int lm = tid >> 1;
    const int lk = (tid & 1) * 8;

    const int gr0 = blockIdx.y << 7;
    const int gc0 = blockIdx.x << 7;

    const float* aPtr = A  + (long)(gr0 + lm) * lda + lk;
    const float* bPtr = Bm + (long)(gc0 + lm) * ldb + lk;

    float acc[2][8][4];
#pragma unroll
    for (int i = 0; i < 2; i++)
#pragma unroll
        for (int j = 0; j < 8; j++)
#pragma unroll
            for (int q = 0; q < 4; q++) acc[i][j][q] = 0.f;

    for (int k0 = 0; k0 < K; k0 += 16) {
        float4 a0 = *(const float4*)(aPtr + k0);
        float4 a1 = *(const float4*)(aPtr + k0 + 4);
        float4 b0 = *(const float4*)(bPtr + k0);
        float4 b1 = *(const float4*)(bPtr + k0 + 4);
        __syncthreads();
        unsigned* ap = &AsU[lm * 17 + lk];
        unsigned* bp = &BsU[lm * 17 + lk];
        ap[0] = f2tf(a0.x); ap[1] = f2tf(a0.y); ap[2] = f2tf(a0.z); ap[3] = f2tf(a0.w);
        ap[4] = f2tf(a1.x); ap[5] = f2tf(a1.y); ap[6] = f2tf(a1.z); ap[7] = f2tf(a1.w);
        bp[0] = f2tf(b0.x); bp[1] = f2tf(b0.y); bp[2] = f2tf(b0.z); bp[3] = f2tf(b0.w);
        bp[4] = f2tf(b1.x); bp[5] = f2tf(b1.y); bp[6] = f2tf(b1.z); bp[7] = f2tf(b1.w);
        __syncthreads();

#pragma unroll
        for (int kk = 0; kk < 16; kk += 8) {
            unsigned afr[2][4], bfr[8][2];
#pragma unroll
            for (int mf = 0; mf < 2; mf++) {
                const int r0 = wm + mf * 16 + g;
                afr[mf][0] = AsU[r0 * 17 + kk + tg];
                afr[mf][1] = AsU[(r0 + 8) * 17 + kk + tg];
                afr[mf][2] = AsU[r0 * 17 + kk + tg + 4];
                afr[mf][3] = AsU[(r0 + 8) * 17 + kk + tg + 4];
            }
#pragma unroll
            for (int nf = 0; nf < 8; nf++) {
                const int c0 = wn + nf * 8 + g;
                bfr[nf][0] = BsU[c0 * 17 + kk + tg];
                bfr[nf][1] = BsU[c0 * 17 + kk + tg + 4];
            }
#pragma unroll
            for (int mf = 0; mf < 2; mf++)
#pragma unroll
                for (int nf = 0; nf < 8; nf++)
                    mma_tf32(acc[mf][nf], afr[mf], bfr[nf]);
        }
    }

#pragma unroll
    for (int mf = 0; mf < 2; mf++) {
#pragma unroll
        for (int nf = 0; nf < 8; nf++) {
            const int rlo = gr0 + wm + mf * 16 + g;
            const int rhi = rlo + 8;
            const int col = gc0 + wn + nf * 8 + 2 * tg;
            float2 vlo = make_float2(acc[mf][nf][0], acc[mf][nf][1]);
            float2 vhi = make_float2(acc[mf][nf][2], acc[mf][nf][3]);
            if (EPI == 1) {
                const float b0v = bias[col], b1v = bias[col + 1];
                vlo.x += b0v; vlo.y += b1v; vhi.x += b0v; vhi.y += b1v;
            } else if (EPI == 2) {
                vlo.x = 1.f / (1.f + __expf(-vlo.x));
                vlo.y = 1.f / (1.f + __expf(-vlo.y));
                vhi.x = 1.f / (1.f + __expf(-vhi.x));
                vhi.y = 1.f / (1.f + __expf(-vhi.y));
            }
            *(float2*)(C + (long)rlo * ldc + col) = vlo;
            *(float2*)(C + (long)rhi * ldc + col) = vhi;
        }
    }
}

// ---------------------------------------------------------------------------
// Fused flash attention with PE gate.
// Per CTA: one (b,h), one 128-row Q tile. Loop over 16 K/V tiles of 128.
//   S = (Q @ K^T) * scale * PEA[b]; online softmax; O += P @ V.
// 256 threads = 8 warps; warp w owns Q rows [16w, 16w+16).
// smem (dynamic, 168KB): Q[128][68] K[128][68] V[128][68] P[128][132] (tf32).
// ---------------------------------------------------------------------------
__global__ void __launch_bounds__(256, 1)
flash_attn(const float* __restrict__ QKVbase, const float* __restrict__ PEAbase,
           float* __restrict__ Obase)
{
    extern __shared__ unsigned sm[];
    unsigned* Qs = sm;                 // stride 68
    unsigned* Ks = Qs + 128 * 68;
    unsigned* Vs = Ks + 128 * 68;
    unsigned* Ps = Vs + 128 * 68;      // stride 132

    const int z = blockIdx.y;
    const int b = z >> 3, h = z & 7;
    const int qbase = blockIdx.x << 7;

    const float* Qg = QKVbase + (long)b * SEQ * 3 * CH + h * HD;
    const float* Kg = Qg + CH;
    const float* Vg = Qg + 2 * CH;
    const float* Pg = PEAbase + (long)b * SEQ * SEQ;

    const int tid  = threadIdx.x;
    const int wid  = tid >> 5;
    const int lane = tid & 31;
    const int g    = lane >> 2;
    const int tg   = lane & 3;
    const int wm   = wid << 4;

    const int lm  = tid >> 1;          // loader row 0..127
    const int lc0 = (tid & 1) * 32;    // loader col base

    // Q tile -> smem (once)
    {
        const float* qp = Qg + (long)(qbase + lm) * (3 * CH) + lc0;
        unsigned* qs = Qs + lm * 68 + lc0;
#pragma unroll
        for (int i = 0; i < 8; i++) {
            float4 v = *(const float4*)(qp + i * 4);
            qs[i*4+0] = f2tf(v.x); qs[i*4+1] = f2tf(v.y);
            qs[i*4+2] = f2tf(v.z); qs[i*4+3] = f2tf(v.w);
        }
    }

    float oacc[8][4];
#pragma unroll
    for (int nf = 0; nf < 8; nf++)
#pragma unroll
        for (int q = 0; q < 4; q++) oacc[nf][q] = 0.f;
    float m_lo = -INFINITY, m_hi = -INFINITY, l_lo = 0.f, l_hi = 0.f;

    const int qr_lo = qbase + wm + g;
    const int qr_hi = qr_lo + 8;
    const float scale = 0.125f;

    for (int kt = 0; kt < SEQ; kt += 128) {
        // ---- K tile: gmem -> regs, sync, -> smem ----
        float4 t[8];
        {
            const float* kp = Kg + (long)(kt + lm) * (3 * CH) + lc0;
#pragma unroll
            for (int i = 0; i < 8; i++) t[i] = *(const float4*)(kp + i * 4);
        }
        __syncthreads();   // prev iter's mma reads of Ks/Vs/Ps done
        {
            unsigned* ks = Ks + lm * 68 + lc0;
#pragma unroll
            for (int i = 0; i < 8; i++) {
                ks[i*4+0] = f2tf(t[i].x); ks[i*4+1] = f2tf(t[i].y);
                ks[i*4+2] = f2tf(t[i].z); ks[i*4+3] = f2tf(t[i].w);
            }
        }
        __syncthreads();

        // ---- V tile: gmem -> smem (overlaps with QK mma below; read after sync3)
        {
            const float* vp = Vg + (long)(kt + lm) * (3 * CH) + lc0;
            unsigned* vs = Vs + lm * 68 + lc0;
#pragma unroll
            for (int i = 0; i < 8; i++) {
                float4 v = *(const float4*)(vp + i * 4);
                vs[i*4+0] = f2tf(v.x); vs[i*4+1] = f2tf(v.y);
                vs[i*4+2] = f2tf(v.z); vs[i*4+3] = f2tf(v.w);
            }
        }

        // ---- S = Q @ K^T  (warp: 16 rows x 128 cols) ----
        float sacc[16][4];
#pragma unroll
        for (int nf = 0; nf < 16; nf++)
#pragma unroll
            for (int q = 0; q < 4; q++) sacc[nf][q] = 0.f;

#pragma unroll
        for (int kk = 0; kk < 64; kk += 8) {
            unsigned afr[4];
            afr[0] = Qs[(wm + g) * 68 + kk + tg];
            afr[1] = Qs[(wm + g + 8) * 68 + kk + tg];
            afr[2] = Qs[(wm + g) * 68 + kk + tg + 4];
            afr[3] = Qs[(wm + g + 8) * 68 + kk + tg + 4];
#pragma unroll
            for (int nf = 0; nf < 16; nf++) {
                unsigned bfr[2];
                bfr[0] = Ks[(nf * 8 + g) * 68 + kk + tg];
                bfr[1] = Ks[(nf * 8 + g) * 68 + kk + tg + 4];
                mma_tf32(sacc[nf], afr, bfr);
            }
        }

        // ---- gate by scale * PEA ----
#pragma unroll
        for (int nf = 0; nf < 16; nf++) {
            const int col = kt + nf * 8 + 2 * tg;
            float2 plo = *(const float2*)(Pg + (long)qr_lo * SEQ + col);
            float2 phi = *(const float2*)(Pg + (long)qr_hi * SEQ + col);
            sacc[nf][0] *= scale * plo.x; sacc[nf][1] *= scale * plo.y;
            sacc[nf][2] *= scale * phi.x; sacc[nf][3] *= scale * phi.y;
        }

        // ---- online softmax ----
        float tm_lo = sacc[0][0], tm_hi = sacc[0][2];
#pragma unroll
        for (int nf = 0; nf < 16; nf++) {
            tm_lo = fmaxf(tm_lo, fmaxf(sacc[nf][0], sacc[nf][1]));
            tm_hi = fmaxf(tm_hi, fmaxf(sacc[nf][2], sacc[nf][3]));
        }
        tm_lo = fmaxf(tm_lo, __shfl_xor_sync(0xffffffffu, tm_lo, 1));
        tm_lo = fmaxf(tm_lo, __shfl_xor_sync(0xffffffffu, tm_lo, 2));
        tm_hi = fmaxf(tm_hi, __shfl_xor_sync(0xffffffffu, tm_hi, 1));
        tm_hi = fmaxf(tm_hi, __shfl_xor_sync(0xffffffffu, tm_hi, 2));

        const float mn_lo = fmaxf(m_lo, tm_lo);
        const float mn_hi = fmaxf(m_hi, tm_hi);
        const float al_lo = __expf(m_lo - mn_lo);
        const float al_hi = __expf(m_hi - mn_hi);
        m_lo = mn_lo; m_hi = mn_hi;

        float rs_lo = 0.f, rs_hi = 0.f;
#pragma unroll
        for (int nf = 0; nf < 16; nf++) {
            float p0 = __expf(sacc[nf][0] - mn_lo);
            float p1 = __expf(sacc[nf][1] - mn_lo);
            float p2 = __expf(sacc[nf][2] - mn_hi);
            float p3 = __expf(sacc[nf][3] - mn_hi);
            rs_lo += p0 + p1; rs_hi += p2 + p3;
            *(uint2*)&Ps[(wm + g) * 132 + nf * 8 + 2 * tg]     = make_uint2(f2tf(p0), f2tf(p1));
            *(uint2*)&Ps[(wm + g + 8) * 132 + nf * 8 + 2 * tg] = make_uint2(f2tf(p2), f2tf(p3));
        }
        rs_lo += __shfl_xor_sync(0xffffffffu, rs_lo, 1);
        rs_lo += __shfl_xor_sync(0xffffffffu, rs_lo, 2);
        rs_hi += __shfl_xor_sync(0xffffffffu, rs_hi, 1);
        rs_hi += __shfl_xor_sync(0xffffffffu, rs_hi, 2);
        l_lo = l_lo * al_lo + rs_lo;
        l_hi = l_hi * al_hi + rs_hi;

#pragma unroll
        for (int nf = 0; nf < 8; nf++) {
            oacc[nf][0] *= al_lo; oacc[nf][1] *= al_lo;
            oacc[nf][2] *= al_hi; oacc[nf][3] *= al_hi;
        }

        __syncthreads();   // V tile complete (P is warp-private)

        // ---- O += P @ V  (warp: 16 rows x 64 cols, k=128) ----
#pragma unroll
        for (int kk = 0; kk < 128; kk += 8) {
            unsigned afr[4];
            afr[0] = Ps[(wm + g) * 132 + kk + tg];
            afr[1] = Ps[(wm + g + 8) * 132 + kk + tg];
            afr[2] = Ps[(wm + g) * 132 + kk + tg + 4];
            afr[3] = Ps[(wm + g + 8) * 132 + kk + tg + 4];
#pragma unroll
            for (int nf = 0; nf < 8; nf++) {
                unsigned bfr[2];
                bfr[0] = Vs[(kk + tg) * 68 + nf * 8 + g];
                bfr[1] = Vs[(kk + tg + 4) * 68 + nf * 8 + g];
                mma_tf32(oacc[nf], afr, bfr);
            }
        }
    }

    // ---- epilogue: O /= l, write ----
    const float inv_lo = 1.f / l_lo;
    const float inv_hi = 1.f / l_hi;
    float* Co = Obase + (long)b * SEQ * CH + h * HD;
#pragma unroll
    for (int nf = 0; nf < 8; nf++) {
        const int col = nf * 8 + 2 * tg;
        *(float2*)(Co + (long)qr_lo * CH + col) =
            make_float2(oacc[nf][0] * inv_lo, oacc[nf][1] * inv_lo);
        *(float2*)(Co + (long)qr_hi * CH + col) =
            make_float2(oacc[nf][2] * inv_hi, oacc[nf][3] * inv_hi);
    }
}

// ---------------------------------------------------------------------------
// GroupNorm split (full-chip, deterministic).
// ---------------------------------------------------------------------------
__global__ void __launch_bounds__(256)
gn_partial(const float* __restrict__ Y, float* __restrict__ part)
{
    const int slab = blockIdx.x;
    const int bg   = blockIdx.y;
    const int b = bg >> 3, g = bg & 7;
    const float* base = Y + (long)b * SEQ * CH + g * CPG;
    const int tid = threadIdx.x;
    const int n0 = slab * 256;

    float s = 0.f, ss = 0.f;
    for (int i = tid; i < 4096; i += 256) {
        const int n = n0 + (i >> 4);
        const int c = (i & 15) * 4;
        float4 v = *(const float4*)(base + (long)n * CH + c);
        s  += v.x + v.y + v.z + v.w;
        ss += v.x * v.x + v.y * v.y + v.z * v.z + v.w * v.w;
    }
    __shared__ float sh1[256], sh2[256];
    sh1[tid] = s; sh2[tid] = ss; __syncthreads();
    for (int st = 128; st > 0; st >>= 1) {
        if (tid < st) { sh1[tid] += sh1[tid + st]; sh2[tid] += sh2[tid + st]; }
        __syncthreads();
    }
    if (tid == 0) {
        part[(bg * 8 + slab) * 2 + 0] = sh1[0];
        part[(bg * 8 + slab) * 2 + 1] = sh2[0];
    }
}

__global__ void __launch_bounds__(256)
gn_apply(float* __restrict__ Y, const float* __restrict__ part,
         const float* __restrict__ gamma, const float* __restrict__ beta)
{
    const int sl = blockIdx.x;
    const int bg = blockIdx.y;
    const int b = bg >> 3, g = bg & 7;
    float* base = Y + (long)b * SEQ * CH + g * CPG;
    const int tid = threadIdx.x;

    float s = 0.f, ss = 0.f;
#pragma unroll
    for (int i = 0; i < 8; i++) {
        s  += part[(bg * 8 + i) * 2 + 0];
        ss += part[(bg * 8 + i) * 2 + 1];
    }
    const float TOT  = (float)(SEQ * CPG);
    const float mean = s / TOT;
    const float var  = ss / TOT - mean * mean;
    const float inv  = rsqrtf(var + 1e-5f);

    const int n0 = sl * 128;
    for (int i = tid; i < 2048; i += 256) {
        const int n = n0 + (i >> 4);
        const int c = (i & 15) * 4;
        float4 v = *(float4*)(base + (long)n * CH + c);
        const int ch = g * CPG + c;
        v.x = (v.x - mean) * inv * gamma[ch]     + beta[ch];
        v.y = (v.y - mean) * inv * gamma[ch + 1] + beta[ch + 1];
        v.z = (v.z - mean) * inv * gamma[ch + 2] + beta[ch + 2];
        v.w = (v.w - mean) * inv * gamma[ch + 3] + beta[ch + 3];
        *(float4*)(base + (long)n * CH + c) = v;
    }
}

// ---------------------------------------------------------------------------
extern "C" void kernel_launch(void* const* d_in, const int* in_sizes, int n_in,
                              void* d_out, int out_size)
{
    const float* x       = (const float*)d_in[0];
    const float* pe      = (const float*)d_in[1];
    const float* qkv_w   = (const float*)d_in[2];
    const float* proj_w  = (const float*)d_in[3];
    const float* proj_b  = (const float*)d_in[4];
    const float* conv1_w = (const float*)d_in[5];
    const float* conv1_b = (const float*)d_in[6];
    const float* gn1_g   = (const float*)d_in[7];
    const float* gn1_b   = (const float*)d_in[8];
    const float* conv2_w = (const float*)d_in[9];
    const float* conv2_b = (const float*)d_in[10];
    const float* gn2_g   = (const float*)d_in[11];
    const float* gn2_b   = (const float*)d_in[12];
    float* out = (float*)d_out;

    float *P1, *P2, *PEA, *QKV, *O, *GNP;
    cudaGetSymbolAddress((void**)&P1,  g_P1);
    cudaGetSymbolAddress((void**)&P2,  g_P2);
    cudaGetSymbolAddress((void**)&PEA, g_PEA);
    cudaGetSymbolAddress((void**)&QKV, g_QKV);
    cudaGetSymbolAddress((void**)&O,   g_O);
    cudaGetSymbolAddress((void**)&GNP, g_GNP);

    const dim3 blk(256);
    const int FA_SMEM = (3 * 128 * 68 + 128 * 132) * 4;   // 172032 B
    cudaFuncSetAttribute(flash_attn, cudaFuncAttributeMaxDynamicSharedMemorySize, FA_SMEM);

    // conv1/conv2 (1x1 conv == GEMM over channels)
    gemm_tf32<1><<<dim3(4, 64, 1), blk>>>(pe, conv1_w, P1, conv1_b,
        512, 512, 512, 512, 0, 0, 0);
    gemm_tf32<1><<<dim3(4, 64, 1), blk>>>(pe, conv2_w, P2, conv2_b,
        512, 512, 512, 512, 0, 0, 0);

    gn_partial<<<dim3(8, 32), blk>>>(P1, GNP);
    gn_apply  <<<dim3(16, 32), blk>>>(P1, GNP, gn1_g, gn1_b);
    gn_partial<<<dim3(8, 32), blk>>>(P2, GNP);
    gn_apply  <<<dim3(16, 32), blk>>>(P2, GNP, gn2_g, gn2_b);

    // pe_attn[b] = sigmoid(P1[b] @ P2[b]^T)
    gemm_tf32<2><<<dim3(16, 16, BATCH), blk>>>(P1, P2, PEA, nullptr,
        512, 512, 512, 2048,
        (long)SEQ * CH, (long)SEQ * CH, (long)SEQ * SEQ);

    // qkv = x @ qkv_w^T
    gemm_tf32<0><<<dim3(12, 64, 1), blk>>>(x, qkv_w, QKV, nullptr,
        512, 512, 512, 3 * CH, 0, 0, 0);

    // fused: S = QK^T * scale * PEA; softmax; O = P @ V
    flash_attn<<<dim3(16, 32), blk, FA_SMEM>>>(QKV, PEA, O);

    // out = O @ proj_w^T + proj_b
    gemm_tf32<1><<<dim3(4, 64, 1), blk>>>(O, proj_w, out, proj_b,
        512, 512, 512, 512, 0, 0, 0);
}